// round 9
// baseline (speedup 1.0000x reference)
#include <cuda_runtime.h>
#include <cstdint>

#define FULL 0xFFFFFFFFu

// Static scratch (no allocations):
__device__ float    g_part[2 * 8 * 32 * 1024]; // [arr(p/m)][split][b][c], 2MB
__device__ float    g_nrm[32];                 // per-b sum of rad^2 (self-reset)
__device__ unsigned g_all   = 0;               // block arrival counter (self-reset)
__device__ unsigned g_rdone = 0;               // reducer-done counter (self-reset)

// Order-preserving float <-> uint mapping (monotone for non-NaN).
__device__ __forceinline__ unsigned f2ord(float f) {
    unsigned b = __float_as_uint(f);
    return (b & 0x80000000u) ? ~b : (b | 0x80000000u);
}
__device__ __forceinline__ float ord2f(unsigned u) {
    unsigned b = (u & 0x80000000u) ? (u ^ 0x80000000u) : ~u;
    return __uint_as_float(b);
}

// Packed fp32x2 FMA (Blackwell FFMA2).
__device__ __forceinline__ unsigned long long ffma2(
    unsigned long long a, unsigned long long b, unsigned long long c) {
    unsigned long long d;
    asm("fma.rn.f32x2 %0, %1, %2, %3;" : "=l"(d) : "l"(a), "l"(b), "l"(c));
    return d;
}

__device__ __forceinline__ float4 f4add(float4 a, float4 b) {
    return make_float4(a.x + b.x, a.y + b.y, a.z + b.z, a.w + b.w);
}

union SmemU {
    struct {
        float Ws[32 * 64];   // [c][k] 8KB
        float FsP[32 * 68];  // max(rad,0), pitch 68
        float FsM[32 * 68];  // min(rad,0)
        float nrm[32];
    } g;
    struct {
        unsigned hist[2048];
        unsigned candT[2048];
        unsigned candB[2048];
        float    red[16];
        unsigned mm[16];
        int      bnd[4];
        unsigned cnt[2];
        float    sum[16];
        float    scal[4];
    } p;
};

// ---------------------------------------------------------------------------
// Single kernel, grid = 256 = 32 ctiles x 8 splits (all co-resident, 1 wave):
//   every block : GEMM partials for (ctile: 32 c, split: 256 k) over 4 chunks
//   ctile==0 && split<4 : also accumulate rad sum-of-squares -> g_nrm
//   split==0 blocks : after all arrivals, run per-batch prep (batch=ctile)
//                     inline + reduce that batch's 64KB of partials -> out
// ---------------------------------------------------------------------------
__global__ void __launch_bounds__(256) fused_kernel(
    const float* __restrict__ f_rad,    // [32,1024]
    const float* __restrict__ f_histo,  // [32,2048]
    const int*   __restrict__ rad_mask, // [32]
    const int*   __restrict__ histo_mask,
    const float* __restrict__ W,        // [1024,2048]
    const float* __restrict__ bias,     // [1024]
    const float* __restrict__ token,    // [1024]
    float* __restrict__ out)            // [32,1024]
{
    __shared__ __align__(16) SmemU sm;

    const int tid  = threadIdx.x;
    const int lane = tid & 31;
    const int wid  = tid >> 5;

    const int ctile = blockIdx.x & 31;
    const int split = blockIdx.x >> 5;
    const int c0    = ctile * 32;
    const bool do_nrm = (ctile == 0) && (split < 4);

    // ================== GEMM phase ==================
    const float4* W4 = (const float4*)W;
    const float4* R4 = (const float4*)f_rad;
    const int kq = tid & 15;    // float4 index along k within chunk
    const int cl = tid >> 4;    // 0..15

    // prefetch chunk 0
    float4 wv[2], rv[2];
    {
        const int kk = split * 256;
        #pragma unroll
        for (int j = 0; j < 2; j++)
            wv[j] = W4[(size_t)(c0 + cl + 16 * j) * 512 + (kk >> 2) + kq];
        const int kb = (kk & 1023) >> 2;
        #pragma unroll
        for (int j = 0; j < 2; j++) {
            int i = tid + 256 * j;
            rv[j] = R4[(size_t)(i >> 4) * 256 + kb + (i & 15)];
        }
    }
    if (tid < 32) sm.g.nrm[tid] = 0.f;
    __syncthreads();

    unsigned long long accp[4], accm[4];
    #pragma unroll
    for (int c = 0; c < 4; c++) { accp[c] = 0ull; accm[c] = 0ull; }

    const int cw = wid * 4;     // warp's 4 c-rows within tile

    #pragma unroll 1
    for (int ch = 0; ch < 4; ch++) {
        // stage current chunk from regs
        #pragma unroll
        for (int j = 0; j < 2; j++)
            *(float4*)&sm.g.Ws[(cl + 16 * j) * 64 + 4 * kq] = wv[j];
        #pragma unroll
        for (int j = 0; j < 2; j++) {
            int i  = tid + 256 * j;
            int bb = i >> 4;
            float4 r = rv[j], p, m;
            p.x = fmaxf(r.x, 0.f); m.x = fminf(r.x, 0.f);
            p.y = fmaxf(r.y, 0.f); m.y = fminf(r.y, 0.f);
            p.z = fmaxf(r.z, 0.f); m.z = fminf(r.z, 0.f);
            p.w = fmaxf(r.w, 0.f); m.w = fminf(r.w, 0.f);
            *(float4*)&sm.g.FsP[bb * 68 + 4 * (i & 15)] = p;
            *(float4*)&sm.g.FsM[bb * 68 + 4 * (i & 15)] = m;
            if (do_nrm)
                atomicAdd(&sm.g.nrm[bb], r.x*r.x + r.y*r.y + r.z*r.z + r.w*r.w);
        }
        __syncthreads();

        // prefetch next chunk (latency hidden by compute below)
        if (ch < 3) {
            const int kn = split * 256 + (ch + 1) * 64;
            #pragma unroll
            for (int j = 0; j < 2; j++)
                wv[j] = W4[(size_t)(c0 + cl + 16 * j) * 512 + (kn >> 2) + kq];
            const int kbn = (kn & 1023) >> 2;
            #pragma unroll
            for (int j = 0; j < 2; j++) {
                int i = tid + 256 * j;
                rv[j] = R4[(size_t)(i >> 4) * 256 + kbn + (i & 15)];
            }
        }

        // microkernel: warp = 4 c-rows, lane = b
        const ulonglong2* wrow = (const ulonglong2*)&sm.g.Ws[cw * 64];
        const ulonglong2* fp   = (const ulonglong2*)&sm.g.FsP[lane * 68];
        const ulonglong2* fm   = (const ulonglong2*)&sm.g.FsM[lane * 68];
        #pragma unroll
        for (int ki = 0; ki < 16; ki++) {
            ulonglong2 a  = fp[ki];
            ulonglong2 b2 = fm[ki];
            #pragma unroll
            for (int c = 0; c < 4; c++) {
                ulonglong2 w = wrow[c * 16 + ki];
                accp[c] = ffma2(w.x, a.x,  accp[c]);
                accp[c] = ffma2(w.y, a.y,  accp[c]);
                accm[c] = ffma2(w.x, b2.x, accm[c]);
                accm[c] = ffma2(w.y, b2.y, accm[c]);
            }
        }
        __syncthreads();   // protect smem before next chunk's stores
    }

    // fold f32x2 halves, store partials (plain STG, no atomics)
    {
        float op[4], om[4];
        #pragma unroll
        for (int c = 0; c < 4; c++) {
            op[c] = __uint_as_float((unsigned)(accp[c] & 0xffffffffull))
                  + __uint_as_float((unsigned)(accp[c] >> 32));
            om[c] = __uint_as_float((unsigned)(accm[c] & 0xffffffffull))
                  + __uint_as_float((unsigned)(accm[c] >> 32));
        }
        float* dp = &g_part[(((size_t)0 * 8 + split) * 32 + lane) * 1024 + c0 + cw];
        float* dm = &g_part[(((size_t)1 * 8 + split) * 32 + lane) * 1024 + c0 + cw];
        *(float4*)dp = make_float4(op[0], op[1], op[2], op[3]);
        *(float4*)dm = make_float4(om[0], om[1], om[2], om[3]);
    }

    // flush rad-norm partials, then announce arrival
    if (do_nrm && tid < 32) atomicAdd(&g_nrm[tid], sm.g.nrm[tid]);
    __threadfence();
    __syncthreads();
    if (tid == 0) atomicAdd(&g_all, 1u);

    if (split != 0) return;

    // ================== REDUCER (one per batch) ==================
    const int b = ctile;
    if (tid == 0) {
        volatile unsigned* pa = &g_all;
        while (*pa < 256u) { __nanosleep(64); }
    }
    __syncthreads();
    __threadfence();   // acquire all partials + g_nrm

    // ---- inline prep for batch b (histogram select over f_histo[b]) ----
    const float* his = f_histo + b * 2048;

    #pragma unroll
    for (int j = 0; j < 8; j++) sm.p.hist[tid + 256 * j] = 0;
    if (tid < 2) sm.p.cnt[tid] = 0;

    float sh = 0.f;
    unsigned v8[8], mx = 0u, mn = 0xFFFFFFFFu;
    #pragma unroll
    for (int j = 0; j < 8; j++) {
        float x = his[tid + 256 * j];
        sh += x * x;
        unsigned o = f2ord(x);
        v8[j] = o; mx = max(mx, o); mn = min(mn, o);
    }
    #pragma unroll
    for (int o = 16; o > 0; o >>= 1) sh += __shfl_xor_sync(FULL, sh, o);
    mx = __reduce_max_sync(FULL, mx);
    mn = __reduce_min_sync(FULL, mn);
    if (lane == 0) { sm.p.red[wid] = sh; sm.p.mm[wid] = mx; sm.p.mm[8 + wid] = mn; }
    __syncthreads();

    #pragma unroll
    for (int j = 0; j < 8; j++) atomicAdd(&sm.p.hist[v8[j] >> 21], 1u);

    if (tid == 0) {
        float c2 = 0.f;
        unsigned MX = 0u, MN = 0xFFFFFFFFu;
        #pragma unroll
        for (int w = 0; w < 8; w++) {
            c2 += sm.p.red[w];
            MX = max(MX, sm.p.mm[w]); MN = min(MN, sm.p.mm[8 + w]);
        }
        sm.p.scal[1] = 1.f / fmaxf(sqrtf(c2), 1e-12f);
        sm.p.mm[0] = MX; sm.p.mm[8] = MN;
    }
    __syncthreads();

    if (wid == 0) {
        int bin = (int)(sm.p.mm[0] >> 21);
        unsigned cum = 0;
        while (true) {
            int ib = bin - lane;
            unsigned c = (ib >= 0) ? sm.p.hist[ib] : 0u;
            unsigned p = c;
            #pragma unroll
            for (int o = 1; o < 32; o <<= 1) {
                unsigned t = __shfl_up_sync(FULL, p, o);
                if (lane >= o) p += t;
            }
            unsigned ball = __ballot_sync(FULL, cum + p >= 16u);
            if (ball) {
                int l = __ffs(ball) - 1;
                unsigned pl = __shfl_sync(FULL, p, l);
                unsigned cc = __shfl_sync(FULL, c, l);
                if (lane == 0) { sm.p.bnd[0] = bin - l; sm.p.bnd[1] = (int)(cum + pl - cc); }
                break;
            }
            cum += __shfl_sync(FULL, p, 31);
            bin -= 32;
        }
    } else if (wid == 1) {
        int bin = (int)(sm.p.mm[8] >> 21);
        unsigned cum = 0;
        while (true) {
            int ib = bin + lane;
            unsigned c = (ib < 2048) ? sm.p.hist[ib] : 0u;
            unsigned p = c;
            #pragma unroll
            for (int o = 1; o < 32; o <<= 1) {
                unsigned t = __shfl_up_sync(FULL, p, o);
                if (lane >= o) p += t;
            }
            unsigned ball = __ballot_sync(FULL, cum + p >= 16u);
            if (ball) {
                int l = __ffs(ball) - 1;
                unsigned pl = __shfl_sync(FULL, p, l);
                unsigned cc = __shfl_sync(FULL, c, l);
                if (lane == 0) { sm.p.bnd[2] = bin + l; sm.p.bnd[3] = (int)(cum + pl - cc); }
                break;
            }
            cum += __shfl_sync(FULL, p, 31);
            bin += 32;
        }
    }
    __syncthreads();

    const int Btop = sm.p.bnd[0];
    const int Bbot = sm.p.bnd[2];

    float sA = 0.f, sB = 0.f;
    #pragma unroll
    for (int j = 0; j < 8; j++) {
        unsigned o = v8[j];
        int bn = (int)(o >> 21);
        if (bn > Btop)       sA += ord2f(o);
        else if (bn == Btop) { unsigned p = atomicAdd(&sm.p.cnt[0], 1u); sm.p.candT[p] = o; }
        if (bn < Bbot)       sB += ord2f(o);
        else if (bn == Bbot) { unsigned p = atomicAdd(&sm.p.cnt[1], 1u); sm.p.candB[p] = o; }
    }
    #pragma unroll
    for (int o = 16; o > 0; o >>= 1) {
        sA += __shfl_xor_sync(FULL, sA, o);
        sB += __shfl_xor_sync(FULL, sB, o);
    }
    if (lane == 0) { sm.p.sum[wid] = sA; sm.p.sum[8 + wid] = sB; }
    __syncthreads();

    if (wid == 0) {
        float sum = 0.f;
        #pragma unroll
        for (int w = 0; w < 8; w++) sum += sm.p.sum[w];
        const int m = 16 - sm.p.bnd[1];
        const int cnt = (int)sm.p.cnt[0];
        for (int pass = 0; pass < m; pass++) {
            unsigned best = 0u;
            for (int i = lane; i < cnt; i += 32) best = max(best, sm.p.candT[i]);
            unsigned wm = __reduce_max_sync(FULL, best);
            sum += ord2f(wm);
            int idx = -1;
            for (int i = lane; i < cnt; i += 32)
                if (sm.p.candT[i] == wm) { idx = i; break; }
            unsigned ball = __ballot_sync(FULL, idx >= 0);
            if (lane == (int)__ffs(ball) - 1) sm.p.candT[idx] = 0u;
        }
        if (lane == 0) sm.p.scal[2] = sum;
    } else if (wid == 1) {
        float sum = 0.f;
        #pragma unroll
        for (int w = 0; w < 8; w++) sum += sm.p.sum[8 + w];
        const int m = 16 - sm.p.bnd[3];
        const int cnt = (int)sm.p.cnt[1];
        for (int pass = 0; pass < m; pass++) {
            unsigned best = 0xFFFFFFFFu;
            for (int i = lane; i < cnt; i += 32) best = min(best, sm.p.candB[i]);
            unsigned wm = __reduce_min_sync(FULL, best);
            sum += ord2f(wm);
            int idx = -1;
            for (int i = lane; i < cnt; i += 32)
                if (sm.p.candB[i] == wm) { idx = i; break; }
            unsigned ball = __ballot_sync(FULL, idx >= 0);
            if (lane == (int)__ffs(ball) - 1) sm.p.candB[idx] = 0xFFFFFFFFu;
        }
        if (lane == 0) sm.p.scal[3] = sum;
    }
    __syncthreads();

    // ---- per-batch reduce: 2 arrays x 8 splits x 1024 c (64KB, L2-hot) ----
    const float inv_r = 1.f / fmaxf(sqrtf(g_nrm[b]), 1e-12f);
    const float Tp = sm.p.scal[1] * sm.p.scal[2] * (1.f / 16.f);
    const float Tn = sm.p.scal[1] * sm.p.scal[3] * (1.f / 16.f);
    const float cp = inv_r * Tp;
    const float cn = inv_r * Tn;
    const float flag = ((rad_mask[b] != 0) && (histo_mask[b] != 0)) ? 0.f : 1.f;

    const float4* P4 = (const float4*)g_part;
    const size_t sstr = 32 * 256;          // split stride (float4)
    const size_t astr = 8 * sstr;          // array stride
    const size_t base = (size_t)b * 256 + tid;

    float4 z = make_float4(0, 0, 0, 0);
    float4 P1 = z, P2 = z, M1 = z, M2 = z;
    #pragma unroll
    for (int s = 0; s < 4; s++) {
        P1 = f4add(P1, P4[base + (size_t)s * sstr]);
        P2 = f4add(P2, P4[base + (size_t)(s + 4) * sstr]);
        M1 = f4add(M1, P4[base + astr + (size_t)s * sstr]);
        M2 = f4add(M2, P4[base + astr + (size_t)(s + 4) * sstr]);
    }

    float4 bs = ((const float4*)bias)[tid];
    float4 tk = ((const float4*)token)[tid];
    float4 o;
    o.x = bs.x + flag * tk.x + cp * (P1.x - M2.x) + cn * (M1.x - P2.x);
    o.y = bs.y + flag * tk.y + cp * (P1.y - M2.y) + cn * (M1.y - P2.y);
    o.z = bs.z + flag * tk.z + cp * (P1.z - M2.z) + cn * (M1.z - P2.z);
    o.w = bs.w + flag * tk.w + cp * (P1.w - M2.w) + cn * (M1.w - P2.w);
    ((float4*)out)[base] = o;

    // ---- self-reset for clean graph replays ----
    __threadfence();
    __syncthreads();
    if (tid == 0) {
        unsigned d = atomicAdd(&g_rdone, 1u);
        if (d == 31u) {                  // last reducer resets globals
            g_all   = 0u;
            g_rdone = 0u;
            #pragma unroll
            for (int i = 0; i < 32; i++) g_nrm[i] = 0.f;
            __threadfence();
        }
    }
}

extern "C" void kernel_launch(void* const* d_in, const int* in_sizes, int n_in,
                              void* d_out, int out_size) {
    const float* f_rad      = (const float*)d_in[0];
    const float* f_histo    = (const float*)d_in[1];
    const int*   rad_mask   = (const int*)  d_in[2];
    const int*   histo_mask = (const int*)  d_in[3];
    const float* W          = (const float*)d_in[4];
    const float* bias       = (const float*)d_in[5];
    const float* token      = (const float*)d_in[6];
    float* out = (float*)d_out;

    fused_kernel<<<256, 256>>>(f_rad, f_histo, rad_mask, histo_mask,
                               W, bias, token, out);
}

// round 10
// speedup vs baseline: 1.6486x; 1.6486x over previous
#include <cuda_runtime.h>
#include <cstdint>

#define FULL 0xFFFFFFFFu

// Static scratch (no allocations):
__device__ float4 g_scal[32];                 // per-b: {inv_r, Tp, Tn, flag}
__device__ float  g_part[2 * 32 * 32 * 1024]; // [arr(p/m)][split][b][c], 8MB

// Order-preserving float <-> uint mapping (monotone for non-NaN).
__device__ __forceinline__ unsigned f2ord(float f) {
    unsigned b = __float_as_uint(f);
    return (b & 0x80000000u) ? ~b : (b | 0x80000000u);
}
__device__ __forceinline__ float ord2f(unsigned u) {
    unsigned b = (u & 0x80000000u) ? (u ^ 0x80000000u) : ~u;
    return __uint_as_float(b);
}

// Packed fp32x2 FMA (Blackwell FFMA2).
__device__ __forceinline__ unsigned long long ffma2(
    unsigned long long a, unsigned long long b, unsigned long long c) {
    unsigned long long d;
    asm("fma.rn.f32x2 %0, %1, %2, %3;" : "=l"(d) : "l"(a), "l"(b), "l"(c));
    return d;
}

// ---------------------------------------------------------------------------
// Fused kernel (UNCHANGED from R7 best): blocks 0..31 = prep,
// blocks 32..543 = scalar-free split-K GEMM partials. NO inter-block deps.
// ---------------------------------------------------------------------------
union SmemU {
    struct {
        unsigned hist[2048];
        unsigned candT[2048];
        unsigned candB[2048];
        float    red[16];
        unsigned mm[16];
        int      bnd[4];
        unsigned cnt[2];
        float    sum[16];
        float    scal[4];
    } p;
    struct {
        float Ws[64 * 64];      // [c][k] 16KB
        float FsP[32 * 68];     // max(rad,0), pitch 68
        float FsM[32 * 68];     // min(rad,0)
    } g;
};

__global__ void __launch_bounds__(256) fused_kernel(
    const float* __restrict__ f_rad,    // [32,1024]
    const float* __restrict__ f_histo,  // [32,2048]
    const int*   __restrict__ rad_mask, // [32]
    const int*   __restrict__ histo_mask,
    const float* __restrict__ W)        // [1024,2048]
{
    __shared__ __align__(16) SmemU sm;

    const int tid  = threadIdx.x;
    const int lane = tid & 31;
    const int wid  = tid >> 5;

    if (blockIdx.x < 32) {
        // ======================= PREP =======================
        const int b = blockIdx.x;
        const float* rad = f_rad   + b * 1024;
        const float* his = f_histo + b * 2048;

        #pragma unroll
        for (int j = 0; j < 8; j++) sm.p.hist[tid + 256 * j] = 0;
        if (tid < 2) sm.p.cnt[tid] = 0;

        float sr = 0.f, sh = 0.f;
        unsigned v8[8], mx = 0u, mn = 0xFFFFFFFFu;
        #pragma unroll
        for (int j = 0; j < 4; j++) { float x = rad[tid + 256 * j]; sr += x * x; }
        #pragma unroll
        for (int j = 0; j < 8; j++) {
            float x = his[tid + 256 * j];
            sh += x * x;
            unsigned o = f2ord(x);
            v8[j] = o; mx = max(mx, o); mn = min(mn, o);
        }
        #pragma unroll
        for (int o = 16; o > 0; o >>= 1) {
            sr += __shfl_xor_sync(FULL, sr, o);
            sh += __shfl_xor_sync(FULL, sh, o);
        }
        mx = __reduce_max_sync(FULL, mx);
        mn = __reduce_min_sync(FULL, mn);
        if (lane == 0) { sm.p.red[wid] = sr; sm.p.red[8 + wid] = sh; sm.p.mm[wid] = mx; sm.p.mm[8 + wid] = mn; }
        __syncthreads();

        #pragma unroll
        for (int j = 0; j < 8; j++) atomicAdd(&sm.p.hist[v8[j] >> 21], 1u);

        if (tid == 0) {
            float a = 0.f, c2 = 0.f;
            unsigned MX = 0u, MN = 0xFFFFFFFFu;
            #pragma unroll
            for (int w = 0; w < 8; w++) {
                a += sm.p.red[w]; c2 += sm.p.red[8 + w];
                MX = max(MX, sm.p.mm[w]); MN = min(MN, sm.p.mm[8 + w]);
            }
            sm.p.scal[0] = 1.f / fmaxf(sqrtf(a),  1e-12f);
            sm.p.scal[1] = 1.f / fmaxf(sqrtf(c2), 1e-12f);
            sm.p.mm[0] = MX; sm.p.mm[8] = MN;
        }
        __syncthreads();

        if (wid == 0) {
            int bin = (int)(sm.p.mm[0] >> 21);
            unsigned cum = 0;
            while (true) {
                int ib = bin - lane;
                unsigned c = (ib >= 0) ? sm.p.hist[ib] : 0u;
                unsigned p = c;
                #pragma unroll
                for (int o = 1; o < 32; o <<= 1) {
                    unsigned t = __shfl_up_sync(FULL, p, o);
                    if (lane >= o) p += t;
                }
                unsigned ball = __ballot_sync(FULL, cum + p >= 16u);
                if (ball) {
                    int l = __ffs(ball) - 1;
                    unsigned pl = __shfl_sync(FULL, p, l);
                    unsigned cl = __shfl_sync(FULL, c, l);
                    if (lane == 0) { sm.p.bnd[0] = bin - l; sm.p.bnd[1] = (int)(cum + pl - cl); }
                    break;
                }
                cum += __shfl_sync(FULL, p, 31);
                bin -= 32;
            }
        } else if (wid == 1) {
            int bin = (int)(sm.p.mm[8] >> 21);
            unsigned cum = 0;
            while (true) {
                int ib = bin + lane;
                unsigned c = (ib < 2048) ? sm.p.hist[ib] : 0u;
                unsigned p = c;
                #pragma unroll
                for (int o = 1; o < 32; o <<= 1) {
                    unsigned t = __shfl_up_sync(FULL, p, o);
                    if (lane >= o) p += t;
                }
                unsigned ball = __ballot_sync(FULL, cum + p >= 16u);
                if (ball) {
                    int l = __ffs(ball) - 1;
                    unsigned pl = __shfl_sync(FULL, p, l);
                    unsigned cl = __shfl_sync(FULL, c, l);
                    if (lane == 0) { sm.p.bnd[2] = bin + l; sm.p.bnd[3] = (int)(cum + pl - cl); }
                    break;
                }
                cum += __shfl_sync(FULL, p, 31);
                bin += 32;
            }
        }
        __syncthreads();

        const int Btop = sm.p.bnd[0];
        const int Bbot = sm.p.bnd[2];

        float sA = 0.f, sB = 0.f;
        #pragma unroll
        for (int j = 0; j < 8; j++) {
            unsigned o = v8[j];
            int bn = (int)(o >> 21);
            if (bn > Btop)       sA += ord2f(o);
            else if (bn == Btop) { unsigned p = atomicAdd(&sm.p.cnt[0], 1u); sm.p.candT[p] = o; }
            if (bn < Bbot)       sB += ord2f(o);
            else if (bn == Bbot) { unsigned p = atomicAdd(&sm.p.cnt[1], 1u); sm.p.candB[p] = o; }
        }
        #pragma unroll
        for (int o = 16; o > 0; o >>= 1) {
            sA += __shfl_xor_sync(FULL, sA, o);
            sB += __shfl_xor_sync(FULL, sB, o);
        }
        if (lane == 0) { sm.p.sum[wid] = sA; sm.p.sum[8 + wid] = sB; }
        __syncthreads();

        if (wid == 0) {
            float sum = 0.f;
            #pragma unroll
            for (int w = 0; w < 8; w++) sum += sm.p.sum[w];
            const int m = 16 - sm.p.bnd[1];
            const int cnt = (int)sm.p.cnt[0];
            for (int pass = 0; pass < m; pass++) {
                unsigned best = 0u;
                for (int i = lane; i < cnt; i += 32) best = max(best, sm.p.candT[i]);
                unsigned wm = __reduce_max_sync(FULL, best);
                sum += ord2f(wm);
                int idx = -1;
                for (int i = lane; i < cnt; i += 32)
                    if (sm.p.candT[i] == wm) { idx = i; break; }
                unsigned ball = __ballot_sync(FULL, idx >= 0);
                if (lane == (int)__ffs(ball) - 1) sm.p.candT[idx] = 0u;
            }
            if (lane == 0) sm.p.scal[2] = sum;
        } else if (wid == 1) {
            float sum = 0.f;
            #pragma unroll
            for (int w = 0; w < 8; w++) sum += sm.p.sum[8 + w];
            const int m = 16 - sm.p.bnd[3];
            const int cnt = (int)sm.p.cnt[1];
            for (int pass = 0; pass < m; pass++) {
                unsigned best = 0xFFFFFFFFu;
                for (int i = lane; i < cnt; i += 32) best = min(best, sm.p.candB[i]);
                unsigned wm = __reduce_min_sync(FULL, best);
                sum += ord2f(wm);
                int idx = -1;
                for (int i = lane; i < cnt; i += 32)
                    if (sm.p.candB[i] == wm) { idx = i; break; }
                unsigned ball = __ballot_sync(FULL, idx >= 0);
                if (lane == (int)__ffs(ball) - 1) sm.p.candB[idx] = 0xFFFFFFFFu;
            }
            if (lane == 0) sm.p.scal[3] = sum;
        }
        __syncthreads();

        if (tid == 0) {
            float flag = ((rad_mask[b] != 0) && (histo_mask[b] != 0)) ? 0.f : 1.f;
            float Tp = sm.p.scal[1] * sm.p.scal[2] * (1.f / 16.f);
            float Tn = sm.p.scal[1] * sm.p.scal[3] * (1.f / 16.f);
            g_scal[b] = make_float4(sm.p.scal[0], Tp, Tn, flag);
        }
    } else {
        // ======================= GEMM (scalar-free partials) =======================
        const int gb    = blockIdx.x - 32;
        const int c0    = (gb & 15) * 64;
        const int split = gb >> 4;
        const int k0    = split * 64;

        const float4* W4 = (const float4*)W;
        const int kq  = tid & 15;
        const int cl  = tid >> 4;
        const int kq0 = k0 >> 2;
        float4 wv[4];
        #pragma unroll
        for (int j = 0; j < 4; j++)
            wv[j] = W4[(size_t)(c0 + cl + 16 * j) * 512 + kq0 + kq];

        const float4* R4 = (const float4*)f_rad;
        const int kb = (k0 & 1023) >> 2;
        float4 rv[2];
        #pragma unroll
        for (int j = 0; j < 2; j++) {
            int i = tid + 256 * j;
            rv[j] = R4[(size_t)(i >> 4) * 256 + kb + (i & 15)];
        }

        #pragma unroll
        for (int j = 0; j < 2; j++) {
            int i  = tid + 256 * j;
            int bb = i >> 4;
            float4 r = rv[j], p, m;
            p.x = fmaxf(r.x, 0.f); m.x = fminf(r.x, 0.f);
            p.y = fmaxf(r.y, 0.f); m.y = fminf(r.y, 0.f);
            p.z = fmaxf(r.z, 0.f); m.z = fminf(r.z, 0.f);
            p.w = fmaxf(r.w, 0.f); m.w = fminf(r.w, 0.f);
            *(float4*)&sm.g.FsP[bb * 68 + 4 * (i & 15)] = p;
            *(float4*)&sm.g.FsM[bb * 68 + 4 * (i & 15)] = m;
        }
        #pragma unroll
        for (int j = 0; j < 4; j++)
            *(float4*)&sm.g.Ws[(cl + 16 * j) * 64 + 4 * kq] = wv[j];
        __syncthreads();

        const int cw = wid * 8;
        const ulonglong2* wrow = (const ulonglong2*)&sm.g.Ws[cw * 64];
        const ulonglong2* fp   = (const ulonglong2*)&sm.g.FsP[lane * 68];
        const ulonglong2* fm   = (const ulonglong2*)&sm.g.FsM[lane * 68];

        unsigned long long accp[8], accm[8];
        #pragma unroll
        for (int c = 0; c < 8; c++) { accp[c] = 0ull; accm[c] = 0ull; }

        #pragma unroll
        for (int ki = 0; ki < 16; ki++) {
            ulonglong2 fpv = fp[ki];
            ulonglong2 fmv = fm[ki];
            #pragma unroll
            for (int c = 0; c < 8; c++) {
                ulonglong2 w = wrow[c * 16 + ki];
                accp[c] = ffma2(w.x, fpv.x, accp[c]);
                accp[c] = ffma2(w.y, fpv.y, accp[c]);
                accm[c] = ffma2(w.x, fmv.x, accm[c]);
                accm[c] = ffma2(w.y, fmv.y, accm[c]);
            }
        }

        float op[8], om[8];
        #pragma unroll
        for (int c = 0; c < 8; c++) {
            op[c] = __uint_as_float((unsigned)(accp[c] & 0xffffffffull))
                  + __uint_as_float((unsigned)(accp[c] >> 32));
            om[c] = __uint_as_float((unsigned)(accm[c] & 0xffffffffull))
                  + __uint_as_float((unsigned)(accm[c] >> 32));
        }
        float* dp = &g_part[(((size_t)0 * 32 + split) * 32 + lane) * 1024 + c0 + cw];
        float* dm = &g_part[(((size_t)1 * 32 + split) * 32 + lane) * 1024 + c0 + cw];
        *(float4*)(dp + 0) = make_float4(op[0], op[1], op[2], op[3]);
        *(float4*)(dp + 4) = make_float4(op[4], op[5], op[6], op[7]);
        *(float4*)(dm + 0) = make_float4(om[0], om[1], om[2], om[3]);
        *(float4*)(dm + 4) = make_float4(om[4], om[5], om[6], om[7]);
    }
}

// ---------------------------------------------------------------------------
// Reduce v2: 256 blocks (32 b x 8 c-chunks of 128), 256 threads.
// Each thread: 8 independent LDG.128 with coefficient folded in at load time:
//   pair p in [0,64): arr = p>>5, s = p&31
//   coeff = sign(s<16) * ( ((arr==0)==(s<16)) ? cp : cn )
// then 8-way smem tree per column; warp-group 0 writes out.
// ---------------------------------------------------------------------------
__global__ void __launch_bounds__(256) reduce_kernel(
    const float* __restrict__ bias,   // [1024]
    const float* __restrict__ token,  // [1024]
    float* __restrict__ out)          // [32,1024]
{
    const int b   = blockIdx.x >> 3;        // batch
    const int cc  = blockIdx.x & 7;         // 128-c chunk (32 float4 cols)
    const int col = threadIdx.x & 31;       // float4 column within chunk
    const int grp = threadIdx.x >> 5;       // 8 groups x 8 pairs each

    __shared__ float4 s_p[8][32];

    float4 sc = g_scal[b];
    const float cp = sc.x * sc.y;   // inv_r * Tp
    const float cn = sc.x * sc.z;   // inv_r * Tn

    const float4* P4 = (const float4*)g_part;
    // float4 index for pair p, this (b, column):
    //   idx = ((arr*32 + s)*32 + b)*256 + cc*32 + col  = p*8192 + b*256 + cc*32 + col
    const size_t base = (size_t)b * 256 + cc * 32 + col;

    // Issue all 8 loads first (MLP), then combine.
    float4 v[8];
    #pragma unroll
    for (int j = 0; j < 8; j++)
        v[j] = P4[base + (size_t)(grp * 8 + j) * 8192];

    float4 acc = make_float4(0, 0, 0, 0);
    #pragma unroll
    for (int j = 0; j < 8; j++) {
        int p   = grp * 8 + j;
        int s   = p & 31;
        int arr = p >> 5;
        bool pos = (s < 16);
        float mag = ((arr == 0) == pos) ? cp : cn;
        float coef = pos ? mag : -mag;
        acc.x += coef * v[j].x;
        acc.y += coef * v[j].y;
        acc.z += coef * v[j].z;
        acc.w += coef * v[j].w;
    }
    s_p[grp][col] = acc;
    __syncthreads();

    if (grp == 0) {
        float4 t = s_p[0][col];
        #pragma unroll
        for (int g = 1; g < 8; g++) {
            float4 u = s_p[g][col];
            t.x += u.x; t.y += u.y; t.z += u.z; t.w += u.w;
        }
        const int bq = cc * 32 + col;           // float4 index within [0,256)
        float4 bs = ((const float4*)bias)[bq];
        float4 tk = ((const float4*)token)[bq];
        const float flag = sc.w;
        float4 o;
        o.x = t.x + bs.x + flag * tk.x;
        o.y = t.y + bs.y + flag * tk.y;
        o.z = t.z + bs.z + flag * tk.z;
        o.w = t.w + bs.w + flag * tk.w;
        ((float4*)out)[base] = o;
    }
}

extern "C" void kernel_launch(void* const* d_in, const int* in_sizes, int n_in,
                              void* d_out, int out_size) {
    const float* f_rad      = (const float*)d_in[0];
    const float* f_histo    = (const float*)d_in[1];
    const int*   rad_mask   = (const int*)  d_in[2];
    const int*   histo_mask = (const int*)  d_in[3];
    const float* W          = (const float*)d_in[4];
    const float* bias       = (const float*)d_in[5];
    const float* token      = (const float*)d_in[6];
    float* out = (float*)d_out;

    fused_kernel<<<544, 256>>>(f_rad, f_histo, rad_mask, histo_mask, W);
    reduce_kernel<<<256, 256>>>(bias, token, out);
}

// round 11
// speedup vs baseline: 1.8243x; 1.1065x over previous
#include <cuda_runtime.h>
#include <cstdint>

#define FULL 0xFFFFFFFFu

// Static scratch (no allocations):
__device__ float4 g_scal[32];                 // per-b: {inv_r, Tp, Tn, flag}
__device__ float  g_part[2 * 16 * 32 * 1024]; // [arr(p/m)][split][b][c], 4MB

// Order-preserving float <-> uint mapping (monotone for non-NaN).
__device__ __forceinline__ unsigned f2ord(float f) {
    unsigned b = __float_as_uint(f);
    return (b & 0x80000000u) ? ~b : (b | 0x80000000u);
}
__device__ __forceinline__ float ord2f(unsigned u) {
    unsigned b = (u & 0x80000000u) ? (u ^ 0x80000000u) : ~u;
    return __uint_as_float(b);
}

// Packed fp32x2 FMA (Blackwell FFMA2).
__device__ __forceinline__ unsigned long long ffma2(
    unsigned long long a, unsigned long long b, unsigned long long c) {
    unsigned long long d;
    asm("fma.rn.f32x2 %0, %1, %2, %3;" : "=l"(d) : "l"(a), "l"(b), "l"(c));
    return d;
}

union SmemU {
    struct {
        unsigned hist[2048];
        unsigned candT[2048];
        unsigned candB[2048];
        float    red[16];
        unsigned mm[16];
        int      bnd[4];
        unsigned cnt[2];
        float    sum[16];
        float    scal[4];
    } p;
    struct {
        float Ws[64 * 64];      // [c][k] 16KB
        float FsP[32 * 68];     // max(rad,0), pitch 68
        float FsM[32 * 68];     // min(rad,0)
    } g;
};

// ---------------------------------------------------------------------------
// Fused kernel, grid = 288:
//   blocks 0..31   : prep (per-batch scalars via histogram select) -> g_scal
//   blocks 32..287 : scalar-free GEMM partials, 64 c x 128 k per block,
//                    processed as 2 chunks of 64 k (all LDGs issued upfront).
// ---------------------------------------------------------------------------
__global__ void __launch_bounds__(256) fused_kernel(
    const float* __restrict__ f_rad,    // [32,1024]
    const float* __restrict__ f_histo,  // [32,2048]
    const int*   __restrict__ rad_mask, // [32]
    const int*   __restrict__ histo_mask,
    const float* __restrict__ W)        // [1024,2048]
{
    __shared__ __align__(16) SmemU sm;

    const int tid  = threadIdx.x;
    const int lane = tid & 31;
    const int wid  = tid >> 5;

    if (blockIdx.x < 32) {
        // ======================= PREP (unchanged, proven) =======================
        const int b = blockIdx.x;
        const float* rad = f_rad   + b * 1024;
        const float* his = f_histo + b * 2048;

        #pragma unroll
        for (int j = 0; j < 8; j++) sm.p.hist[tid + 256 * j] = 0;
        if (tid < 2) sm.p.cnt[tid] = 0;

        float sr = 0.f, sh = 0.f;
        unsigned v8[8], mx = 0u, mn = 0xFFFFFFFFu;
        #pragma unroll
        for (int j = 0; j < 4; j++) { float x = rad[tid + 256 * j]; sr += x * x; }
        #pragma unroll
        for (int j = 0; j < 8; j++) {
            float x = his[tid + 256 * j];
            sh += x * x;
            unsigned o = f2ord(x);
            v8[j] = o; mx = max(mx, o); mn = min(mn, o);
        }
        #pragma unroll
        for (int o = 16; o > 0; o >>= 1) {
            sr += __shfl_xor_sync(FULL, sr, o);
            sh += __shfl_xor_sync(FULL, sh, o);
        }
        mx = __reduce_max_sync(FULL, mx);
        mn = __reduce_min_sync(FULL, mn);
        if (lane == 0) { sm.p.red[wid] = sr; sm.p.red[8 + wid] = sh; sm.p.mm[wid] = mx; sm.p.mm[8 + wid] = mn; }
        __syncthreads();

        #pragma unroll
        for (int j = 0; j < 8; j++) atomicAdd(&sm.p.hist[v8[j] >> 21], 1u);

        if (tid == 0) {
            float a = 0.f, c2 = 0.f;
            unsigned MX = 0u, MN = 0xFFFFFFFFu;
            #pragma unroll
            for (int w = 0; w < 8; w++) {
                a += sm.p.red[w]; c2 += sm.p.red[8 + w];
                MX = max(MX, sm.p.mm[w]); MN = min(MN, sm.p.mm[8 + w]);
            }
            sm.p.scal[0] = 1.f / fmaxf(sqrtf(a),  1e-12f);
            sm.p.scal[1] = 1.f / fmaxf(sqrtf(c2), 1e-12f);
            sm.p.mm[0] = MX; sm.p.mm[8] = MN;
        }
        __syncthreads();

        if (wid == 0) {
            int bin = (int)(sm.p.mm[0] >> 21);
            unsigned cum = 0;
            while (true) {
                int ib = bin - lane;
                unsigned c = (ib >= 0) ? sm.p.hist[ib] : 0u;
                unsigned p = c;
                #pragma unroll
                for (int o = 1; o < 32; o <<= 1) {
                    unsigned t = __shfl_up_sync(FULL, p, o);
                    if (lane >= o) p += t;
                }
                unsigned ball = __ballot_sync(FULL, cum + p >= 16u);
                if (ball) {
                    int l = __ffs(ball) - 1;
                    unsigned pl = __shfl_sync(FULL, p, l);
                    unsigned cl = __shfl_sync(FULL, c, l);
                    if (lane == 0) { sm.p.bnd[0] = bin - l; sm.p.bnd[1] = (int)(cum + pl - cl); }
                    break;
                }
                cum += __shfl_sync(FULL, p, 31);
                bin -= 32;
            }
        } else if (wid == 1) {
            int bin = (int)(sm.p.mm[8] >> 21);
            unsigned cum = 0;
            while (true) {
                int ib = bin + lane;
                unsigned c = (ib < 2048) ? sm.p.hist[ib] : 0u;
                unsigned p = c;
                #pragma unroll
                for (int o = 1; o < 32; o <<= 1) {
                    unsigned t = __shfl_up_sync(FULL, p, o);
                    if (lane >= o) p += t;
                }
                unsigned ball = __ballot_sync(FULL, cum + p >= 16u);
                if (ball) {
                    int l = __ffs(ball) - 1;
                    unsigned pl = __shfl_sync(FULL, p, l);
                    unsigned cl = __shfl_sync(FULL, c, l);
                    if (lane == 0) { sm.p.bnd[2] = bin + l; sm.p.bnd[3] = (int)(cum + pl - cl); }
                    break;
                }
                cum += __shfl_sync(FULL, p, 31);
                bin += 32;
            }
        }
        __syncthreads();

        const int Btop = sm.p.bnd[0];
        const int Bbot = sm.p.bnd[2];

        float sA = 0.f, sB = 0.f;
        #pragma unroll
        for (int j = 0; j < 8; j++) {
            unsigned o = v8[j];
            int bn = (int)(o >> 21);
            if (bn > Btop)       sA += ord2f(o);
            else if (bn == Btop) { unsigned p = atomicAdd(&sm.p.cnt[0], 1u); sm.p.candT[p] = o; }
            if (bn < Bbot)       sB += ord2f(o);
            else if (bn == Bbot) { unsigned p = atomicAdd(&sm.p.cnt[1], 1u); sm.p.candB[p] = o; }
        }
        #pragma unroll
        for (int o = 16; o > 0; o >>= 1) {
            sA += __shfl_xor_sync(FULL, sA, o);
            sB += __shfl_xor_sync(FULL, sB, o);
        }
        if (lane == 0) { sm.p.sum[wid] = sA; sm.p.sum[8 + wid] = sB; }
        __syncthreads();

        if (wid == 0) {
            float sum = 0.f;
            #pragma unroll
            for (int w = 0; w < 8; w++) sum += sm.p.sum[w];
            const int m = 16 - sm.p.bnd[1];
            const int cnt = (int)sm.p.cnt[0];
            for (int pass = 0; pass < m; pass++) {
                unsigned best = 0u;
                for (int i = lane; i < cnt; i += 32) best = max(best, sm.p.candT[i]);
                unsigned wm = __reduce_max_sync(FULL, best);
                sum += ord2f(wm);
                int idx = -1;
                for (int i = lane; i < cnt; i += 32)
                    if (sm.p.candT[i] == wm) { idx = i; break; }
                unsigned ball = __ballot_sync(FULL, idx >= 0);
                if (lane == (int)__ffs(ball) - 1) sm.p.candT[idx] = 0u;
            }
            if (lane == 0) sm.p.scal[2] = sum;
        } else if (wid == 1) {
            float sum = 0.f;
            #pragma unroll
            for (int w = 0; w < 8; w++) sum += sm.p.sum[8 + w];
            const int m = 16 - sm.p.bnd[3];
            const int cnt = (int)sm.p.cnt[1];
            for (int pass = 0; pass < m; pass++) {
                unsigned best = 0xFFFFFFFFu;
                for (int i = lane; i < cnt; i += 32) best = min(best, sm.p.candB[i]);
                unsigned wm = __reduce_min_sync(FULL, best);
                sum += ord2f(wm);
                int idx = -1;
                for (int i = lane; i < cnt; i += 32)
                    if (sm.p.candB[i] == wm) { idx = i; break; }
                unsigned ball = __ballot_sync(FULL, idx >= 0);
                if (lane == (int)__ffs(ball) - 1) sm.p.candB[idx] = 0xFFFFFFFFu;
            }
            if (lane == 0) sm.p.scal[3] = sum;
        }
        __syncthreads();

        if (tid == 0) {
            float flag = ((rad_mask[b] != 0) && (histo_mask[b] != 0)) ? 0.f : 1.f;
            float Tp = sm.p.scal[1] * sm.p.scal[2] * (1.f / 16.f);
            float Tn = sm.p.scal[1] * sm.p.scal[3] * (1.f / 16.f);
            g_scal[b] = make_float4(sm.p.scal[0], Tp, Tn, flag);
        }
    } else {
        // ============ GEMM: 64 c x 128 k per block, 2 chunks of 64 k ============
        const int gb    = blockIdx.x - 32;
        const int c0    = (gb & 15) * 64;
        const int split = gb >> 4;           // 0..15
        const int k0    = split * 128;

        // ---- issue ALL global loads upfront (W both chunks + rad both chunks)
        const float4* W4 = (const float4*)W;
        const int kq  = tid & 15;
        const int cl  = tid >> 4;
        const int kq0 = k0 >> 2;             // float4 col base chunk0; +16 chunk1
        float4 wv[2][4];
        #pragma unroll
        for (int ch = 0; ch < 2; ch++)
            #pragma unroll
            for (int j = 0; j < 4; j++)
                wv[ch][j] = W4[(size_t)(c0 + cl + 16 * j) * 512 + kq0 + 16 * ch + kq];

        const float4* R4 = (const float4*)f_rad;
        const int kb = (k0 & 1023) >> 2;
        float4 rv[2][2];
        #pragma unroll
        for (int ch = 0; ch < 2; ch++)
            #pragma unroll
            for (int j = 0; j < 2; j++) {
                int i = tid + 256 * j;
                rv[ch][j] = R4[(size_t)(i >> 4) * 256 + kb + 16 * ch + (i & 15)];
            }

        unsigned long long accp[8], accm[8];
        #pragma unroll
        for (int c = 0; c < 8; c++) { accp[c] = 0ull; accm[c] = 0ull; }
        const int cw = wid * 8;

        #pragma unroll
        for (int ch = 0; ch < 2; ch++) {
            if (ch == 1) __syncthreads();    // protect smem before restage
            // stage chunk
            #pragma unroll
            for (int j = 0; j < 2; j++) {
                int i  = tid + 256 * j;
                int bb = i >> 4;
                float4 r = rv[ch][j], p, m;
                p.x = fmaxf(r.x, 0.f); m.x = fminf(r.x, 0.f);
                p.y = fmaxf(r.y, 0.f); m.y = fminf(r.y, 0.f);
                p.z = fmaxf(r.z, 0.f); m.z = fminf(r.z, 0.f);
                p.w = fmaxf(r.w, 0.f); m.w = fminf(r.w, 0.f);
                *(float4*)&sm.g.FsP[bb * 68 + 4 * (i & 15)] = p;
                *(float4*)&sm.g.FsM[bb * 68 + 4 * (i & 15)] = m;
            }
            #pragma unroll
            for (int j = 0; j < 4; j++)
                *(float4*)&sm.g.Ws[(cl + 16 * j) * 64 + 4 * kq] = wv[ch][j];
            __syncthreads();

            // compute chunk
            const ulonglong2* wrow = (const ulonglong2*)&sm.g.Ws[cw * 64];
            const ulonglong2* fp   = (const ulonglong2*)&sm.g.FsP[lane * 68];
            const ulonglong2* fm   = (const ulonglong2*)&sm.g.FsM[lane * 68];
            #pragma unroll
            for (int ki = 0; ki < 16; ki++) {
                ulonglong2 fpv = fp[ki];
                ulonglong2 fmv = fm[ki];
                #pragma unroll
                for (int c = 0; c < 8; c++) {
                    ulonglong2 w = wrow[c * 16 + ki];
                    accp[c] = ffma2(w.x, fpv.x, accp[c]);
                    accp[c] = ffma2(w.y, fpv.y, accp[c]);
                    accm[c] = ffma2(w.x, fmv.x, accm[c]);
                    accm[c] = ffma2(w.y, fmv.y, accm[c]);
                }
            }
        }

        // fold halves, plain stores
        float op[8], om[8];
        #pragma unroll
        for (int c = 0; c < 8; c++) {
            op[c] = __uint_as_float((unsigned)(accp[c] & 0xffffffffull))
                  + __uint_as_float((unsigned)(accp[c] >> 32));
            om[c] = __uint_as_float((unsigned)(accm[c] & 0xffffffffull))
                  + __uint_as_float((unsigned)(accm[c] >> 32));
        }
        float* dp = &g_part[(((size_t)0 * 16 + split) * 32 + lane) * 1024 + c0 + cw];
        float* dm = &g_part[(((size_t)1 * 16 + split) * 32 + lane) * 1024 + c0 + cw];
        *(float4*)(dp + 0) = make_float4(op[0], op[1], op[2], op[3]);
        *(float4*)(dp + 4) = make_float4(op[4], op[5], op[6], op[7]);
        *(float4*)(dm + 0) = make_float4(om[0], om[1], om[2], om[3]);
        *(float4*)(dm + 4) = make_float4(om[4], om[5], om[6], om[7]);
    }
}

// ---------------------------------------------------------------------------
// Reduce v3: 256 blocks (32 b x 8 c-chunks of 128), 256 threads.
// 32 (arr,split) pairs; each of 8 thread-groups handles 4 pairs with the
// coefficient folded in at load time, then 8-way smem tree per column.
//   pair p: arr = p>>4, s = p&15; pos = (s < 8);
//   coeff = (pos ? +1 : -1) * ( ((arr==0)==pos) ? cp : cn )
// ---------------------------------------------------------------------------
__global__ void __launch_bounds__(256) reduce_kernel(
    const float* __restrict__ bias,   // [1024]
    const float* __restrict__ token,  // [1024]
    float* __restrict__ out)          // [32,1024]
{
    const int b   = blockIdx.x >> 3;        // batch
    const int cc  = blockIdx.x & 7;         // 128-c chunk (32 float4 cols)
    const int col = threadIdx.x & 31;       // float4 column within chunk
    const int grp = threadIdx.x >> 5;       // 8 groups x 4 pairs each

    __shared__ float4 s_p[8][32];

    float4 sc = g_scal[b];
    const float cp = sc.x * sc.y;   // inv_r * Tp
    const float cn = sc.x * sc.z;   // inv_r * Tn

    const float4* P4 = (const float4*)g_part;
    // float4 index for pair p at (b, col): p*8192 + b*256 + cc*32 + col
    const size_t base = (size_t)b * 256 + cc * 32 + col;

    float4 v[4];
    #pragma unroll
    for (int j = 0; j < 4; j++)
        v[j] = P4[base + (size_t)(grp * 4 + j) * 8192];

    float4 acc = make_float4(0, 0, 0, 0);
    #pragma unroll
    for (int j = 0; j < 4; j++) {
        int p   = grp * 4 + j;
        int s   = p & 15;
        int arr = p >> 4;
        bool pos = (s < 8);
        float mag  = ((arr == 0) == pos) ? cp : cn;
        float coef = pos ? mag : -mag;
        acc.x += coef * v[j].x;
        acc.y += coef * v[j].y;
        acc.z += coef * v[j].z;
        acc.w += coef * v[j].w;
    }
    s_p[grp][col] = acc;
    __syncthreads();

    if (grp == 0) {
        float4 t = s_p[0][col];
        #pragma unroll
        for (int g = 1; g < 8; g++) {
            float4 u = s_p[g][col];
            t.x += u.x; t.y += u.y; t.z += u.z; t.w += u.w;
        }
        const int bq = cc * 32 + col;
        float4 bs = ((const float4*)bias)[bq];
        float4 tk = ((const float4*)token)[bq];
        const float flag = sc.w;
        float4 o;
        o.x = t.x + bs.x + flag * tk.x;
        o.y = t.y + bs.y + flag * tk.y;
        o.z = t.z + bs.z + flag * tk.z;
        o.w = t.w + bs.w + flag * tk.w;
        ((float4*)out)[base] = o;
    }
}

extern "C" void kernel_launch(void* const* d_in, const int* in_sizes, int n_in,
                              void* d_out, int out_size) {
    const float* f_rad      = (const float*)d_in[0];
    const float* f_histo    = (const float*)d_in[1];
    const int*   rad_mask   = (const int*)  d_in[2];
    const int*   histo_mask = (const int*)  d_in[3];
    const float* W          = (const float*)d_in[4];
    const float* bias       = (const float*)d_in[5];
    const float* token      = (const float*)d_in[6];
    float* out = (float*)d_out;

    fused_kernel<<<288, 256>>>(f_rad, f_histo, rad_mask, histo_mask, W);
    reduce_kernel<<<256, 256>>>(bias, token, out);
}